// round 16
// baseline (speedup 1.0000x reference)
#include <cuda_runtime.h>
#include <cuda_fp16.h>
#include <cstdint>
#include <cfloat>

// ---------------------------------------------------------------- constants
#define NROWS  16384
#define DIM    128
#define KCODES 8192
#define GATE    0.10f

#define NCHUNK  8            // code chunks per row-block
#define CTILES  16           // 64-code tiles per chunk (128 total / 8)
#define NN_GRID (128 * NCHUNK)
#define RS_GRID 1024

#define OUT_Q    0
#define OUT_IND  (NROWS * DIM)
#define OUT_LOSS (NROWS * DIM + NROWS)
#define GATHER_BLOCKS (NROWS / 8)

// smem layout. Rows padded: 128 fp16 = 256B data + 16B pad = 272B.
#define ROWB    272
#define A_BLKB  (128 * ROWB)          // 34816 : A [128 rows]
#define B_BLKB  (64 * ROWB)           // 17408 : B tile [64 codes]
#define A_OFF   0
#define B_OFF   A_BLKB                // 2 buffers x 17408
#define E2_OFF  (B_OFF + 2 * B_BLKB)  // 2 x 256B
#define NN_SMEM (E2_OFF + 1024)       // 70656

// ------------------------------------------------------------- device scratch
__device__ __half g_Ahi[NROWS * DIM];
__device__ __half g_Bh[KCODES * DIM];
__device__ float g_xn[NROWS * DIM];
__device__ float g_e2[KCODES];
// partials transposed: [chunk][row] for coalesced combine reads
__device__ float g_pb1[(size_t)NCHUNK * NROWS];
__device__ float g_pb2[(size_t)NCHUNK * NROWS];
__device__ int   g_pi1[(size_t)NCHUNK * NROWS];
__device__ float g_b1[NROWS];
__device__ int   g_final[NROWS];
__device__ float g_part[GATHER_BLOCKS];
__device__ int   g_count;
__device__ int   g_list[NROWS];
__device__ float g_tmin[(size_t)NROWS * 128];   // per-row, per-64-code-tile min

// ------------------------------------------------------------- PTX helpers
__device__ __forceinline__ uint32_t smem_to_u32(const void* p) {
    uint32_t a;
    asm("{ .reg .u64 t; cvta.to.shared.u64 t, %1; cvt.u32.u64 %0, t; }"
        : "=r"(a) : "l"(p));
    return a;
}
#define CP_ASYNC16(dst, src) \
    asm volatile("cp.async.cg.shared.global [%0], [%1], 16;" \
                 :: "r"(dst), "l"(src) : "memory")
#define CP_COMMIT() asm volatile("cp.async.commit_group;" ::: "memory")
#define CP_WAIT0()  asm volatile("cp.async.wait_group 0;" ::: "memory")

#define LDSM_X4(r0, r1, r2, r3, addr) \
    asm volatile("ldmatrix.sync.aligned.m8n8.x4.shared.b16 {%0,%1,%2,%3}, [%4];" \
                 : "=r"(r0), "=r"(r1), "=r"(r2), "=r"(r3) : "r"(addr))

__device__ __forceinline__ void mma16816(float* c, const uint32_t* a,
                                         uint32_t b0, uint32_t b1) {
    asm volatile(
        "mma.sync.aligned.m16n8k16.row.col.f32.f16.f16.f32 "
        "{%0,%1,%2,%3}, {%4,%5,%6,%7}, {%8,%9}, {%0,%1,%2,%3};"
        : "+f"(c[0]), "+f"(c[1]), "+f"(c[2]), "+f"(c[3])
        : "r"(a[0]), "r"(a[1]), "r"(a[2]), "r"(a[3]), "r"(b0), "r"(b1));
}

// ---------------------------------------------------------------------------
// Kernel A: fused prep. blocks [0, 2048): layernorm x; [2048, 3072): codebook.
// ---------------------------------------------------------------------------
__global__ __launch_bounds__(256) void prep_kernel(const float* __restrict__ x,
                                                   const float* __restrict__ cb) {
    if (blockIdx.x == 0 && threadIdx.x == 0) g_count = 0;
    int warp = threadIdx.x >> 5, lane = threadIdx.x & 31;
    if (blockIdx.x < NROWS / 8) {
        int row = blockIdx.x * 8 + warp;
        float4 v = *(const float4*)&x[(size_t)row * DIM + lane * 4];
        float s = v.x + v.y + v.z + v.w;
        #pragma unroll
        for (int o = 16; o > 0; o >>= 1) s += __shfl_xor_sync(0xffffffffu, s, o);
        float mu = s * (1.0f / 128.0f);
        float dx = v.x - mu, dy = v.y - mu, dz = v.z - mu, dw = v.w - mu;
        float q = dx * dx + dy * dy + dz * dz + dw * dw;
        #pragma unroll
        for (int o = 16; o > 0; o >>= 1) q += __shfl_xor_sync(0xffffffffu, q, o);
        float rs = rsqrtf(q * (1.0f / 128.0f) + 1e-5f);
        float y[4] = {dx * rs, dy * rs, dz * rs, dw * rs};
        *(float4*)&g_xn[(size_t)row * DIM + lane * 4] =
            make_float4(y[0], y[1], y[2], y[3]);
        __half h[4] = {__float2half(y[0]), __float2half(y[1]),
                       __float2half(y[2]), __float2half(y[3])};
        *(uint2*)&g_Ahi[(size_t)row * DIM + lane * 4] = *(uint2*)h;
    } else {
        int row = (blockIdx.x - NROWS / 8) * 8 + warp;
        float4 v = *(const float4*)&cb[(size_t)row * DIM + lane * 4];
        float q = v.x * v.x + v.y * v.y + v.z * v.z + v.w * v.w;
        #pragma unroll
        for (int o = 16; o > 0; o >>= 1) q += __shfl_xor_sync(0xffffffffu, q, o);
        if (lane == 0) g_e2[row] = q;
        __half h[4] = {__float2half(v.x), __float2half(v.y),
                       __float2half(v.z), __float2half(v.w)};
        *(uint2*)&g_Bh[(size_t)row * DIM + lane * 4] = *(uint2*)h;
    }
}

// ---------------------------------------------------------------------------
// Kernel C: HMMA fp16 hi-only GEMM, static grid, occupancy 2 (unchanged).
// ---------------------------------------------------------------------------
__global__ __launch_bounds__(256, 2) void nn_kernel() {
    extern __shared__ char sptr[];
    const uint32_t sbase = smem_to_u32(sptr);
    const int tid = threadIdx.x;
    const int lane = tid & 31;
    const int w = tid >> 5;
    const int mrow = w * 16;
    const int chunk = blockIdx.x >> 7;          // chunk-major: L2 B-tile reuse
    const int rb = blockIdx.x & 127;
    const int row0 = rb * 128;
    const int tile0 = chunk * CTILES;           // in 64-code tiles

    // A tile: 128 rows
    #pragma unroll
    for (int i = 0; i < 8; i++) {
        int idx = i * 256 + tid;
        int r = (idx >> 4) & 127;
        int u = idx & 15;
        uint4 v = *(const uint4*)(g_Ahi + (size_t)(row0 + r) * DIM + u * 8);
        *(uint4*)(sptr + A_OFF + r * ROWB + u * 16) = v;
    }
    // B tile tile0 (64 codes) + e2 slot 0
    {
        uint32_t bb = sbase + B_OFF;
        const size_t crow0 = (size_t)tile0 * 64;
        #pragma unroll
        for (int i = 0; i < 4; i++) {
            int idx = i * 256 + tid;
            int r = idx >> 4;          // 0..63
            int u = idx & 15;
            CP_ASYNC16(bb + r * ROWB + u * 16, g_Bh + (crow0 + r) * DIM + u * 8);
        }
        if (tid < 16)
            CP_ASYNC16(sbase + E2_OFF + tid * 16,
                       (const char*)(g_e2 + tile0 * 64) + tid * 16);
        CP_COMMIT();
    }

    const uint32_t a_row = mrow + (lane & 15);
    const uint32_t a_cb = (lane >> 4) << 4;
    const uint32_t b_row = (lane & 7) + ((lane & 16) >> 1);
    const uint32_t b_k8 = (lane & 8);

    // ---- hoist A fragments (needs A smem ready)
    __syncthreads();
    uint32_t af[8][4];
    #pragma unroll
    for (int j = 0; j < 8; j++) {
        uint32_t addr = sbase + A_OFF + a_row * ROWB + j * 32 + a_cb;
        LDSM_X4(af[j][0], af[j][1], af[j][2], af[j][3], addr);
    }

    float B1[2], B2[2];
    int I1[2];
    #pragma unroll
    for (int s = 0; s < 2; s++) { B1[s] = FLT_MAX; B2[s] = FLT_MAX; I1[s] = 0; }

    for (int t = 0; t < CTILES; t++) {
        const int gt = tile0 + t;       // global 64-code tile index (0..127)
        CP_WAIT0();
        __syncthreads();
        if (t + 1 < CTILES) {
            uint32_t bb = sbase + B_OFF + ((t + 1) & 1) * B_BLKB;
            const size_t crow0 = (size_t)(gt + 1) * 64;
            #pragma unroll
            for (int i = 0; i < 4; i++) {
                int idx = i * 256 + tid;
                int r = idx >> 4;
                int u = idx & 15;
                CP_ASYNC16(bb + r * ROWB + u * 16, g_Bh + (crow0 + r) * DIM + u * 8);
            }
            if (tid < 16)
                CP_ASYNC16(sbase + E2_OFF + ((t + 1) & 1) * 256 + tid * 16,
                           (const char*)(g_e2 + (gt + 1) * 64) + tid * 16);
            CP_COMMIT();
        }

        const uint32_t bufB = sbase + B_OFF + (t & 1) * B_BLKB;
        float c[8][4];
        #pragma unroll
        for (int nb = 0; nb < 8; nb++)
            #pragma unroll
            for (int q = 0; q < 4; q++) c[nb][q] = 0.0f;

        #pragma unroll
        for (int j = 0; j < 8; j++) {
            const int kk = j * 16;
            uint32_t b[4][4];
            #pragma unroll
            for (int nb4 = 0; nb4 < 4; nb4++) {
                uint32_t addr = bufB +
                                (b_row + nb4 * 16) * ROWB + (kk + b_k8) * 2;
                LDSM_X4(b[nb4][0], b[nb4][1], b[nb4][2], b[nb4][3], addr);
            }
            #pragma unroll
            for (int nb = 0; nb < 8; nb++)
                mma16816(c[nb], af[j],
                         b[nb >> 1][(nb & 1) * 2], b[nb >> 1][(nb & 1) * 2 + 1]);
        }

        const float* e2p = (const float*)(sptr + E2_OFF + (t & 1) * 256);
        const int colb = 2 * (lane & 3);
        float tm[2] = {FLT_MAX, FLT_MAX};
        #pragma unroll
        for (int nb = 0; nb < 8; nb++) {
            float2 ev = *(const float2*)&e2p[colb + nb * 8];
            int gidx = gt * 64 + colb + nb * 8;
            #pragma unroll
            for (int s = 0; s < 2; s++) {       // s=0: row lane>>2, s=1: +8
                float d0 = fmaf(-2.0f, c[nb][s * 2 + 0], ev.x);
                float d1 = fmaf(-2.0f, c[nb][s * 2 + 1], ev.y);
                tm[s] = fminf(tm[s], fminf(d0, d1));
                if (d0 < B1[s]) { B2[s] = B1[s]; B1[s] = d0; I1[s] = gidx; }
                else if (d0 < B2[s]) { B2[s] = d0; }
                if (d1 < B1[s]) { B2[s] = B1[s]; B1[s] = d1; I1[s] = gidx + 1; }
                else if (d1 < B2[s]) { B2[s] = d1; }
            }
        }
        #pragma unroll
        for (int s = 0; s < 2; s++) {
            float m = tm[s];
            m = fminf(m, __shfl_xor_sync(0xffffffffu, m, 1));
            m = fminf(m, __shfl_xor_sync(0xffffffffu, m, 2));
            if ((lane & 3) == 0) {
                int rl = mrow + s * 8 + (lane >> 2);
                g_tmin[(size_t)(row0 + rl) * 128 + gt] = m;
            }
        }
    }

    // merge across the 4 lanes sharing each row; write chunk partials
    #pragma unroll
    for (int s = 0; s < 2; s++) {
        #pragma unroll
        for (int off = 1; off < 4; off <<= 1) {
            float ob1 = __shfl_xor_sync(0xffffffffu, B1[s], off);
            float ob2 = __shfl_xor_sync(0xffffffffu, B2[s], off);
            int oi1 = __shfl_xor_sync(0xffffffffu, I1[s], off);
            float nb2 = fminf(fminf(B2[s], ob2), fmaxf(B1[s], ob1));
            if (ob1 < B1[s] || (ob1 == B1[s] && oi1 < I1[s])) { B1[s] = ob1; I1[s] = oi1; }
            B2[s] = nb2;
        }
        if ((lane & 3) == 0) {
            int row = row0 + mrow + s * 8 + (lane >> 2);
            size_t e = (size_t)chunk * NROWS + row;   // transposed layout
            g_pb1[e] = B1[s];
            g_pb2[e] = B2[s];
            g_pi1[e] = I1[s];
        }
    }
}

// ---------------------------------------------------------------------------
// Kernel D0: combine chunk partials (coalesced reads), gate, compact.
// ---------------------------------------------------------------------------
__global__ __launch_bounds__(128) void combine_kernel() {
    int row = blockIdx.x * 128 + threadIdx.x;
    float B1v = FLT_MAX, B2v = FLT_MAX;
    int I1v = 0x7fffffff;
    #pragma unroll
    for (int c = 0; c < NCHUNK; c++) {
        size_t e = (size_t)c * NROWS + row;
        float b1 = g_pb1[e], b2 = g_pb2[e];
        int i1 = g_pi1[e];
        if (b1 < B1v || (b1 == B1v && i1 < I1v)) {
            B2v = fminf(B1v, b2);
            B1v = b1; I1v = i1;
        } else {
            B2v = fminf(B2v, b1);
        }
    }
    g_b1[row] = B1v;
    if (B2v - B1v >= GATE) {
        g_final[row] = I1v;
    } else {
        int pos = atomicAdd(&g_count, 1);
        g_list[pos] = row;
    }
}

// ---------------------------------------------------------------------------
// Kernel D1: candidate-filtered exact rescan. 256 threads = 4 groups of 64
// lanes, each rescoring one candidate 64-code tile concurrently; stride loop
// over compacted entries.
// ---------------------------------------------------------------------------
__global__ __launch_bounds__(256) void rescan_kernel(const float* __restrict__ cb) {
    const int tid = threadIdx.x;
    const int count = g_count;

    __shared__ float xs[DIM];
    __shared__ int clist[128];
    __shared__ int ccount;
    __shared__ float rv[256];
    __shared__ int   ri[256];

    for (int e = blockIdx.x; e < count; e += RS_GRID) {
        const int row = g_list[e];
        if (tid == 0) ccount = 0;
        if (tid < 128) xs[tid] = g_xn[(size_t)row * DIM + tid];
        __syncthreads();

        if (tid < 128) {
            const float thr = g_b1[row] + GATE;
            float m = g_tmin[(size_t)row * 128 + tid];
            if (m < thr) { int p = atomicAdd(&ccount, 1); clist[p] = tid; }
        }
        __syncthreads();
        const int nc = ccount;

        float best = FLT_MAX;
        int bidx = 0x7fffffff;
        for (int i = (tid >> 6); i < nc; i += 4) {
            int h = clist[i];
            int code = h * 64 + (tid & 63);
            const float4* cp = (const float4*)&cb[(size_t)code * DIM];
            float s0 = 0.f, s1 = 0.f, s2 = 0.f, s3 = 0.f;
            #pragma unroll
            for (int d = 0; d < 32; d += 4) {
                float4 v0 = cp[d + 0], v1 = cp[d + 1], v2 = cp[d + 2], v3 = cp[d + 3];
                s0 = fmaf(v0.x, xs[d * 4 + 0], s0);  s0 = fmaf(v0.y, xs[d * 4 + 1], s0);
                s0 = fmaf(v0.z, xs[d * 4 + 2], s0);  s0 = fmaf(v0.w, xs[d * 4 + 3], s0);
                s1 = fmaf(v1.x, xs[d * 4 + 4], s1);  s1 = fmaf(v1.y, xs[d * 4 + 5], s1);
                s1 = fmaf(v1.z, xs[d * 4 + 6], s1);  s1 = fmaf(v1.w, xs[d * 4 + 7], s1);
                s2 = fmaf(v2.x, xs[d * 4 + 8], s2);  s2 = fmaf(v2.y, xs[d * 4 + 9], s2);
                s2 = fmaf(v2.z, xs[d * 4 + 10], s2); s2 = fmaf(v2.w, xs[d * 4 + 11], s2);
                s3 = fmaf(v3.x, xs[d * 4 + 12], s3); s3 = fmaf(v3.y, xs[d * 4 + 13], s3);
                s3 = fmaf(v3.z, xs[d * 4 + 14], s3); s3 = fmaf(v3.w, xs[d * 4 + 15], s3);
            }
            float dot = (s0 + s1) + (s2 + s3);
            float dist = fmaf(-2.0f, dot, g_e2[code]);
            if (dist < best || (dist == best && code < bidx)) { best = dist; bidx = code; }
        }
        rv[tid] = best; ri[tid] = bidx;
        __syncthreads();
        for (int o = 128; o > 0; o >>= 1) {
            if (tid < o) {
                float v = rv[tid + o]; int ii = ri[tid + o];
                if (v < rv[tid] || (v == rv[tid] && ii < ri[tid])) { rv[tid] = v; ri[tid] = ii; }
            }
            __syncthreads();
        }
        if (tid == 0) g_final[row] = ri[0];
        __syncthreads();   // protect shared reuse on next iteration
    }
}

// ---------------------------------------------------------------------------
// Kernel E: gather + per-block loss partials (deterministic).
// ---------------------------------------------------------------------------
__global__ __launch_bounds__(256) void gather_kernel(const float* __restrict__ cb,
                                                     float* __restrict__ out) {
    __shared__ float sw[8];
    int warp = threadIdx.x >> 5, lane = threadIdx.x & 31;
    int row = blockIdx.x * 8 + warp;
    int ind = g_final[row];
    float4 c = *(const float4*)&cb[(size_t)ind * DIM + lane * 4];
    float4 xv = *(const float4*)&g_xn[(size_t)row * DIM + lane * 4];
    *(float4*)&out[OUT_Q + (size_t)row * DIM + lane * 4] = c;
    float dx = c.x - xv.x, dy = c.y - xv.y, dz = c.z - xv.z, dw = c.w - xv.w;
    float s = dx * dx + dy * dy + dz * dz + dw * dw;
    #pragma unroll
    for (int o = 16; o > 0; o >>= 1) s += __shfl_xor_sync(0xffffffffu, s, o);
    if (lane == 0) { out[OUT_IND + row] = (float)ind; sw[warp] = s; }
    __syncthreads();
    if (threadIdx.x == 0) {
        float tot = 0.0f;
        #pragma unroll
        for (int w = 0; w < 8; w++) tot += sw[w];
        g_part[blockIdx.x] = tot;
    }
}

__global__ __launch_bounds__(256) void final_kernel(float* __restrict__ out) {
    __shared__ float sp[256];
    int tid = threadIdx.x;
    float s = 0.0f;
    for (int i = tid; i < GATHER_BLOCKS; i += 256) s += g_part[i];
    sp[tid] = s;
    __syncthreads();
    for (int o = 128; o > 0; o >>= 1) {
        if (tid < o) sp[tid] += sp[tid + o];
        __syncthreads();
    }
    if (tid == 0) out[OUT_LOSS] = sp[0] * (1.0f / (float)(NROWS * DIM));
}

// ---------------------------------------------------------------------------
extern "C" void kernel_launch(void* const* d_in, const int* in_sizes, int n_in,
                              void* d_out, int out_size) {
    const float* x = (const float*)d_in[0];
    const float* cb = (const float*)d_in[1];
    float* out = (float*)d_out;

    cudaFuncSetAttribute(nn_kernel, cudaFuncAttributeMaxDynamicSharedMemorySize,
                         NN_SMEM);

    prep_kernel<<<NROWS / 8 + KCODES / 8, 256>>>(x, cb);
    nn_kernel<<<NN_GRID, 256, NN_SMEM>>>();
    combine_kernel<<<NROWS / 128, 128>>>();
    rescan_kernel<<<RS_GRID, 256>>>(cb);
    gather_kernel<<<GATHER_BLOCKS, 256>>>(cb, out);
    final_kernel<<<1, 256>>>(out);
}

// round 17
// speedup vs baseline: 1.0178x; 1.0178x over previous
#include <cuda_runtime.h>
#include <cuda_fp16.h>
#include <cstdint>
#include <cfloat>

// ---------------------------------------------------------------- constants
#define NROWS  16384
#define DIM    128
#define KCODES 8192
#define GATE    0.08f

#define NCHUNK  8            // code chunks per row-block
#define CTILES  16           // 64-code tiles per chunk (128 total / 8)
#define NN_GRID (128 * NCHUNK)
#define RS_GRID 2048

#define OUT_Q    0
#define OUT_IND  (NROWS * DIM)
#define OUT_LOSS (NROWS * DIM + NROWS)
#define GATHER_BLOCKS (NROWS / 8)

// smem layout. Rows padded: 128 fp16 = 256B data + 16B pad = 272B.
#define ROWB    272
#define A_BLKB  (128 * ROWB)          // 34816 : A [128 rows]
#define B_BLKB  (64 * ROWB)           // 17408 : B tile [64 codes]
#define A_OFF   0
#define B_OFF   A_BLKB                // 2 buffers x 17408
#define E2_OFF  (B_OFF + 2 * B_BLKB)  // 2 x 256B
#define NN_SMEM (E2_OFF + 1024)       // 70656

// ------------------------------------------------------------- device scratch
__device__ __half g_Ahi[NROWS * DIM];
__device__ __half g_Bh[KCODES * DIM];
__device__ float g_xn[NROWS * DIM];
__device__ float g_e2[KCODES];
// partials transposed: [chunk][row] for coalesced combine reads
__device__ float g_pb1[(size_t)NCHUNK * NROWS];
__device__ float g_pb2[(size_t)NCHUNK * NROWS];
__device__ int   g_pi1[(size_t)NCHUNK * NROWS];
__device__ float g_b1[NROWS];
__device__ int   g_final[NROWS];
__device__ float g_part[GATHER_BLOCKS];
__device__ int   g_count;
__device__ int   g_list[NROWS];
__device__ float g_tmin[(size_t)NROWS * 128];   // per-row, per-64-code-tile min

// ------------------------------------------------------------- PTX helpers
__device__ __forceinline__ uint32_t smem_to_u32(const void* p) {
    uint32_t a;
    asm("{ .reg .u64 t; cvta.to.shared.u64 t, %1; cvt.u32.u64 %0, t; }"
        : "=r"(a) : "l"(p));
    return a;
}
#define CP_ASYNC16(dst, src) \
    asm volatile("cp.async.cg.shared.global [%0], [%1], 16;" \
                 :: "r"(dst), "l"(src) : "memory")
#define CP_COMMIT() asm volatile("cp.async.commit_group;" ::: "memory")
#define CP_WAIT0()  asm volatile("cp.async.wait_group 0;" ::: "memory")

#define LDSM_X4(r0, r1, r2, r3, addr) \
    asm volatile("ldmatrix.sync.aligned.m8n8.x4.shared.b16 {%0,%1,%2,%3}, [%4];" \
                 : "=r"(r0), "=r"(r1), "=r"(r2), "=r"(r3) : "r"(addr))

__device__ __forceinline__ void mma16816(float* c, const uint32_t* a,
                                         uint32_t b0, uint32_t b1) {
    asm volatile(
        "mma.sync.aligned.m16n8k16.row.col.f32.f16.f16.f32 "
        "{%0,%1,%2,%3}, {%4,%5,%6,%7}, {%8,%9}, {%0,%1,%2,%3};"
        : "+f"(c[0]), "+f"(c[1]), "+f"(c[2]), "+f"(c[3])
        : "r"(a[0]), "r"(a[1]), "r"(a[2]), "r"(a[3]), "r"(b0), "r"(b1));
}

// ---------------------------------------------------------------------------
// Kernel A: fused prep. blocks [0, 2048): layernorm x; [2048, 3072): codebook.
// ---------------------------------------------------------------------------
__global__ __launch_bounds__(256) void prep_kernel(const float* __restrict__ x,
                                                   const float* __restrict__ cb) {
    if (blockIdx.x == 0 && threadIdx.x == 0) g_count = 0;
    int warp = threadIdx.x >> 5, lane = threadIdx.x & 31;
    if (blockIdx.x < NROWS / 8) {
        int row = blockIdx.x * 8 + warp;
        float4 v = *(const float4*)&x[(size_t)row * DIM + lane * 4];
        float s = v.x + v.y + v.z + v.w;
        #pragma unroll
        for (int o = 16; o > 0; o >>= 1) s += __shfl_xor_sync(0xffffffffu, s, o);
        float mu = s * (1.0f / 128.0f);
        float dx = v.x - mu, dy = v.y - mu, dz = v.z - mu, dw = v.w - mu;
        float q = dx * dx + dy * dy + dz * dz + dw * dw;
        #pragma unroll
        for (int o = 16; o > 0; o >>= 1) q += __shfl_xor_sync(0xffffffffu, q, o);
        float rs = rsqrtf(q * (1.0f / 128.0f) + 1e-5f);
        float y[4] = {dx * rs, dy * rs, dz * rs, dw * rs};
        *(float4*)&g_xn[(size_t)row * DIM + lane * 4] =
            make_float4(y[0], y[1], y[2], y[3]);
        __half h[4] = {__float2half(y[0]), __float2half(y[1]),
                       __float2half(y[2]), __float2half(y[3])};
        *(uint2*)&g_Ahi[(size_t)row * DIM + lane * 4] = *(uint2*)h;
    } else {
        int row = (blockIdx.x - NROWS / 8) * 8 + warp;
        float4 v = *(const float4*)&cb[(size_t)row * DIM + lane * 4];
        float q = v.x * v.x + v.y * v.y + v.z * v.z + v.w * v.w;
        #pragma unroll
        for (int o = 16; o > 0; o >>= 1) q += __shfl_xor_sync(0xffffffffu, q, o);
        if (lane == 0) g_e2[row] = q;
        __half h[4] = {__float2half(v.x), __float2half(v.y),
                       __float2half(v.z), __float2half(v.w)};
        *(uint2*)&g_Bh[(size_t)row * DIM + lane * 4] = *(uint2*)h;
    }
}

// ---------------------------------------------------------------------------
// Kernel C: HMMA fp16 hi-only GEMM, static grid, occupancy 2 (unchanged).
// ---------------------------------------------------------------------------
__global__ __launch_bounds__(256, 2) void nn_kernel() {
    extern __shared__ char sptr[];
    const uint32_t sbase = smem_to_u32(sptr);
    const int tid = threadIdx.x;
    const int lane = tid & 31;
    const int w = tid >> 5;
    const int mrow = w * 16;
    const int chunk = blockIdx.x >> 7;          // chunk-major: L2 B-tile reuse
    const int rb = blockIdx.x & 127;
    const int row0 = rb * 128;
    const int tile0 = chunk * CTILES;           // in 64-code tiles

    // A tile: 128 rows
    #pragma unroll
    for (int i = 0; i < 8; i++) {
        int idx = i * 256 + tid;
        int r = (idx >> 4) & 127;
        int u = idx & 15;
        uint4 v = *(const uint4*)(g_Ahi + (size_t)(row0 + r) * DIM + u * 8);
        *(uint4*)(sptr + A_OFF + r * ROWB + u * 16) = v;
    }
    // B tile tile0 (64 codes) + e2 slot 0
    {
        uint32_t bb = sbase + B_OFF;
        const size_t crow0 = (size_t)tile0 * 64;
        #pragma unroll
        for (int i = 0; i < 4; i++) {
            int idx = i * 256 + tid;
            int r = idx >> 4;          // 0..63
            int u = idx & 15;
            CP_ASYNC16(bb + r * ROWB + u * 16, g_Bh + (crow0 + r) * DIM + u * 8);
        }
        if (tid < 16)
            CP_ASYNC16(sbase + E2_OFF + tid * 16,
                       (const char*)(g_e2 + tile0 * 64) + tid * 16);
        CP_COMMIT();
    }

    const uint32_t a_row = mrow + (lane & 15);
    const uint32_t a_cb = (lane >> 4) << 4;
    const uint32_t b_row = (lane & 7) + ((lane & 16) >> 1);
    const uint32_t b_k8 = (lane & 8);

    // ---- hoist A fragments (needs A smem ready)
    __syncthreads();
    uint32_t af[8][4];
    #pragma unroll
    for (int j = 0; j < 8; j++) {
        uint32_t addr = sbase + A_OFF + a_row * ROWB + j * 32 + a_cb;
        LDSM_X4(af[j][0], af[j][1], af[j][2], af[j][3], addr);
    }

    float B1[2], B2[2];
    int I1[2];
    #pragma unroll
    for (int s = 0; s < 2; s++) { B1[s] = FLT_MAX; B2[s] = FLT_MAX; I1[s] = 0; }

    for (int t = 0; t < CTILES; t++) {
        const int gt = tile0 + t;       // global 64-code tile index (0..127)
        CP_WAIT0();
        __syncthreads();
        if (t + 1 < CTILES) {
            uint32_t bb = sbase + B_OFF + ((t + 1) & 1) * B_BLKB;
            const size_t crow0 = (size_t)(gt + 1) * 64;
            #pragma unroll
            for (int i = 0; i < 4; i++) {
                int idx = i * 256 + tid;
                int r = idx >> 4;
                int u = idx & 15;
                CP_ASYNC16(bb + r * ROWB + u * 16, g_Bh + (crow0 + r) * DIM + u * 8);
            }
            if (tid < 16)
                CP_ASYNC16(sbase + E2_OFF + ((t + 1) & 1) * 256 + tid * 16,
                           (const char*)(g_e2 + (gt + 1) * 64) + tid * 16);
            CP_COMMIT();
        }

        const uint32_t bufB = sbase + B_OFF + (t & 1) * B_BLKB;
        float c[8][4];
        #pragma unroll
        for (int nb = 0; nb < 8; nb++)
            #pragma unroll
            for (int q = 0; q < 4; q++) c[nb][q] = 0.0f;

        #pragma unroll
        for (int j = 0; j < 8; j++) {
            const int kk = j * 16;
            uint32_t b[4][4];
            #pragma unroll
            for (int nb4 = 0; nb4 < 4; nb4++) {
                uint32_t addr = bufB +
                                (b_row + nb4 * 16) * ROWB + (kk + b_k8) * 2;
                LDSM_X4(b[nb4][0], b[nb4][1], b[nb4][2], b[nb4][3], addr);
            }
            #pragma unroll
            for (int nb = 0; nb < 8; nb++)
                mma16816(c[nb], af[j],
                         b[nb >> 1][(nb & 1) * 2], b[nb >> 1][(nb & 1) * 2 + 1]);
        }

        const float* e2p = (const float*)(sptr + E2_OFF + (t & 1) * 256);
        const int colb = 2 * (lane & 3);
        float tm[2] = {FLT_MAX, FLT_MAX};
        #pragma unroll
        for (int nb = 0; nb < 8; nb++) {
            float2 ev = *(const float2*)&e2p[colb + nb * 8];
            int gidx = gt * 64 + colb + nb * 8;
            #pragma unroll
            for (int s = 0; s < 2; s++) {       // s=0: row lane>>2, s=1: +8
                float d0 = fmaf(-2.0f, c[nb][s * 2 + 0], ev.x);
                float d1 = fmaf(-2.0f, c[nb][s * 2 + 1], ev.y);
                tm[s] = fminf(tm[s], fminf(d0, d1));
                if (d0 < B1[s]) { B2[s] = B1[s]; B1[s] = d0; I1[s] = gidx; }
                else if (d0 < B2[s]) { B2[s] = d0; }
                if (d1 < B1[s]) { B2[s] = B1[s]; B1[s] = d1; I1[s] = gidx + 1; }
                else if (d1 < B2[s]) { B2[s] = d1; }
            }
        }
        #pragma unroll
        for (int s = 0; s < 2; s++) {
            float m = tm[s];
            m = fminf(m, __shfl_xor_sync(0xffffffffu, m, 1));
            m = fminf(m, __shfl_xor_sync(0xffffffffu, m, 2));
            if ((lane & 3) == 0) {
                int rl = mrow + s * 8 + (lane >> 2);
                g_tmin[(size_t)(row0 + rl) * 128 + gt] = m;
            }
        }
    }

    // merge across the 4 lanes sharing each row; write chunk partials
    #pragma unroll
    for (int s = 0; s < 2; s++) {
        #pragma unroll
        for (int off = 1; off < 4; off <<= 1) {
            float ob1 = __shfl_xor_sync(0xffffffffu, B1[s], off);
            float ob2 = __shfl_xor_sync(0xffffffffu, B2[s], off);
            int oi1 = __shfl_xor_sync(0xffffffffu, I1[s], off);
            float nb2 = fminf(fminf(B2[s], ob2), fmaxf(B1[s], ob1));
            if (ob1 < B1[s] || (ob1 == B1[s] && oi1 < I1[s])) { B1[s] = ob1; I1[s] = oi1; }
            B2[s] = nb2;
        }
        if ((lane & 3) == 0) {
            int row = row0 + mrow + s * 8 + (lane >> 2);
            size_t e = (size_t)chunk * NROWS + row;   // transposed layout
            g_pb1[e] = B1[s];
            g_pb2[e] = B2[s];
            g_pi1[e] = I1[s];
        }
    }
}

// ---------------------------------------------------------------------------
// Kernel D0: combine chunk partials (coalesced reads), gate, compact.
// ---------------------------------------------------------------------------
__global__ __launch_bounds__(128) void combine_kernel() {
    int row = blockIdx.x * 128 + threadIdx.x;
    float B1v = FLT_MAX, B2v = FLT_MAX;
    int I1v = 0x7fffffff;
    #pragma unroll
    for (int c = 0; c < NCHUNK; c++) {
        size_t e = (size_t)c * NROWS + row;
        float b1 = g_pb1[e], b2 = g_pb2[e];
        int i1 = g_pi1[e];
        if (b1 < B1v || (b1 == B1v && i1 < I1v)) {
            B2v = fminf(B1v, b2);
            B1v = b1; I1v = i1;
        } else {
            B2v = fminf(B2v, b1);
        }
    }
    g_b1[row] = B1v;
    if (B2v - B1v >= GATE) {
        g_final[row] = I1v;
    } else {
        int pos = atomicAdd(&g_count, 1);
        g_list[pos] = row;
    }
}

// ---------------------------------------------------------------------------
// Kernel D1: candidate-filtered exact rescan. Fixed grid 2048 x 128, stride
// loop over compacted entries (R15 structure).
// ---------------------------------------------------------------------------
__global__ __launch_bounds__(128) void rescan_kernel(const float* __restrict__ cb) {
    const int tid = threadIdx.x;
    const int count = g_count;

    __shared__ float xs[DIM];
    __shared__ int clist[128];
    __shared__ int ccount;
    __shared__ float rv[128];
    __shared__ int   ri[128];

    for (int e = blockIdx.x; e < count; e += RS_GRID) {
        const int row = g_list[e];
        if (tid == 0) ccount = 0;
        xs[tid] = g_xn[(size_t)row * DIM + tid];
        __syncthreads();

        const float thr = g_b1[row] + GATE;
        float m = g_tmin[(size_t)row * 128 + tid];
        if (m < thr) { int p = atomicAdd(&ccount, 1); clist[p] = tid; }
        __syncthreads();
        const int nc = ccount;

        float best = FLT_MAX;
        int bidx = 0x7fffffff;
        for (int i = (tid >> 6); i < nc; i += 2) {
            int h = clist[i];
            int code = h * 64 + (tid & 63);
            const float4* cp = (const float4*)&cb[(size_t)code * DIM];
            float s0 = 0.f, s1 = 0.f, s2 = 0.f, s3 = 0.f;
            #pragma unroll
            for (int d = 0; d < 32; d += 4) {
                float4 v0 = cp[d + 0], v1 = cp[d + 1], v2 = cp[d + 2], v3 = cp[d + 3];
                s0 = fmaf(v0.x, xs[d * 4 + 0], s0);  s0 = fmaf(v0.y, xs[d * 4 + 1], s0);
                s0 = fmaf(v0.z, xs[d * 4 + 2], s0);  s0 = fmaf(v0.w, xs[d * 4 + 3], s0);
                s1 = fmaf(v1.x, xs[d * 4 + 4], s1);  s1 = fmaf(v1.y, xs[d * 4 + 5], s1);
                s1 = fmaf(v1.z, xs[d * 4 + 6], s1);  s1 = fmaf(v1.w, xs[d * 4 + 7], s1);
                s2 = fmaf(v2.x, xs[d * 4 + 8], s2);  s2 = fmaf(v2.y, xs[d * 4 + 9], s2);
                s2 = fmaf(v2.z, xs[d * 4 + 10], s2); s2 = fmaf(v2.w, xs[d * 4 + 11], s2);
                s3 = fmaf(v3.x, xs[d * 4 + 12], s3); s3 = fmaf(v3.y, xs[d * 4 + 13], s3);
                s3 = fmaf(v3.z, xs[d * 4 + 14], s3); s3 = fmaf(v3.w, xs[d * 4 + 15], s3);
            }
            float dot = (s0 + s1) + (s2 + s3);
            float dist = fmaf(-2.0f, dot, g_e2[code]);
            if (dist < best || (dist == best && code < bidx)) { best = dist; bidx = code; }
        }
        rv[tid] = best; ri[tid] = bidx;
        __syncthreads();
        for (int o = 64; o > 0; o >>= 1) {
            if (tid < o) {
                float v = rv[tid + o]; int ii = ri[tid + o];
                if (v < rv[tid] || (v == rv[tid] && ii < ri[tid])) { rv[tid] = v; ri[tid] = ii; }
            }
            __syncthreads();
        }
        if (tid == 0) g_final[row] = ri[0];
        __syncthreads();   // protect shared reuse on next iteration
    }
}

// ---------------------------------------------------------------------------
// Kernel E: gather + per-block loss partials (deterministic).
// ---------------------------------------------------------------------------
__global__ __launch_bounds__(256) void gather_kernel(const float* __restrict__ cb,
                                                     float* __restrict__ out) {
    __shared__ float sw[8];
    int warp = threadIdx.x >> 5, lane = threadIdx.x & 31;
    int row = blockIdx.x * 8 + warp;
    int ind = g_final[row];
    float4 c = *(const float4*)&cb[(size_t)ind * DIM + lane * 4];
    float4 xv = *(const float4*)&g_xn[(size_t)row * DIM + lane * 4];
    *(float4*)&out[OUT_Q + (size_t)row * DIM + lane * 4] = c;
    float dx = c.x - xv.x, dy = c.y - xv.y, dz = c.z - xv.z, dw = c.w - xv.w;
    float s = dx * dx + dy * dy + dz * dz + dw * dw;
    #pragma unroll
    for (int o = 16; o > 0; o >>= 1) s += __shfl_xor_sync(0xffffffffu, s, o);
    if (lane == 0) { out[OUT_IND + row] = (float)ind; sw[warp] = s; }
    __syncthreads();
    if (threadIdx.x == 0) {
        float tot = 0.0f;
        #pragma unroll
        for (int w = 0; w < 8; w++) tot += sw[w];
        g_part[blockIdx.x] = tot;
    }
}

__global__ __launch_bounds__(256) void final_kernel(float* __restrict__ out) {
    __shared__ float sp[256];
    int tid = threadIdx.x;
    float s = 0.0f;
    for (int i = tid; i < GATHER_BLOCKS; i += 256) s += g_part[i];
    sp[tid] = s;
    __syncthreads();
    for (int o = 128; o > 0; o >>= 1) {
        if (tid < o) sp[tid] += sp[tid + o];
        __syncthreads();
    }
    if (tid == 0) out[OUT_LOSS] = sp[0] * (1.0f / (float)(NROWS * DIM));
}

// ---------------------------------------------------------------------------
extern "C" void kernel_launch(void* const* d_in, const int* in_sizes, int n_in,
                              void* d_out, int out_size) {
    const float* x = (const float*)d_in[0];
    const float* cb = (const float*)d_in[1];
    float* out = (float*)d_out;

    cudaFuncSetAttribute(nn_kernel, cudaFuncAttributeMaxDynamicSharedMemorySize,
                         NN_SMEM);

    prep_kernel<<<NROWS / 8 + KCODES / 8, 256>>>(x, cb);
    nn_kernel<<<NN_GRID, 256, NN_SMEM>>>();
    combine_kernel<<<NROWS / 128, 128>>>();
    rescan_kernel<<<RS_GRID, 128>>>(cb);
    gather_kernel<<<GATHER_BLOCKS, 256>>>(cb, out);
    final_kernel<<<1, 256>>>(out);
}